// round 13
// baseline (speedup 1.0000x reference)
#include <cuda_runtime.h>
#include <cuda_fp16.h>
#include <cstdint>
#include <math.h>

#define AST 164   // act row stride (u32); 164%32=4 -> ldmatrix 16B chunks conflict-free
#define MROWS 64  // rays per CTA

// fp16 weights pre-swizzled into per-lane fragment order:
// 256-wide layers: [S16][g:4][v:4][lane:32][4 u32], cw0: [S16][g:4][v:2][lane:32][4 u32]
// vector v holds {b0(nf=2v), b1(nf=2v), b0(nf=2v+1), b1(nf=2v+1)} for mma.m16n8k16.
__device__ uint32_t g_w[264192];

#define OFF_W00 0
#define OFF_W01 8192
#define OFF_W02 40960
#define OFF_W03 73728
#define OFF_W10 106496
#define OFF_W11 147456
#define OFF_W12 180224
#define OFF_W13 212992
#define OFF_CW0 245760
#define W_TOTAL 264192

__device__ __forceinline__ void mma_f16(float* c, const uint32_t* a, uint32_t b0, uint32_t b1){
  asm volatile("mma.sync.aligned.m16n8k16.row.col.f32.f16.f16.f32 "
    "{%0,%1,%2,%3},{%4,%5,%6,%7},{%8,%9},{%0,%1,%2,%3};\n"
    : "+f"(c[0]),"+f"(c[1]),"+f"(c[2]),"+f"(c[3])
    : "r"(a[0]),"r"(a[1]),"r"(a[2]),"r"(a[3]),"r"(b0),"r"(b1));
}

__device__ __forceinline__ void ldsm4(uint32_t* r, uint32_t saddr){
  asm volatile("ldmatrix.sync.aligned.m8n8.x4.shared.b16 {%0,%1,%2,%3}, [%4];"
    : "=r"(r[0]), "=r"(r[1]), "=r"(r[2]), "=r"(r[3]) : "r"(saddr));
}

__global__ void prep_all(const float* __restrict__ w00, const float* __restrict__ w01,
                         const float* __restrict__ w02, const float* __restrict__ w03,
                         const float* __restrict__ w10, const float* __restrict__ w11,
                         const float* __restrict__ w12, const float* __restrict__ w13,
                         const float* __restrict__ cw0)
{
  int i = blockIdx.x * blockDim.x + threadIdx.x;
  if (i >= W_TOTAL) return;
  const float* src; int Kreal, N, off;
  if      (i < OFF_W01){ src=w00; Kreal= 63; N=256; off=OFF_W00; }
  else if (i < OFF_W02){ src=w01; Kreal=256; N=256; off=OFF_W01; }
  else if (i < OFF_W03){ src=w02; Kreal=256; N=256; off=OFF_W02; }
  else if (i < OFF_W10){ src=w03; Kreal=256; N=256; off=OFF_W03; }
  else if (i < OFF_W11){ src=w10; Kreal=319; N=256; off=OFF_W10; }
  else if (i < OFF_W12){ src=w11; Kreal=256; N=256; off=OFF_W11; }
  else if (i < OFF_W13){ src=w12; Kreal=256; N=256; off=OFF_W12; }
  else if (i < OFF_CW0){ src=w13; Kreal=256; N=256; off=OFF_W13; }
  else                 { src=cw0; Kreal=283; N=128; off=OFF_CW0; }
  int local = i - off;
  int u, l, v, g, s, nwb;
  if (N == 256){
    u = local & 3; l = (local >> 2) & 31; v = (local >> 7) & 3;
    g = (local >> 9) & 3; s = local >> 11; nwb = g * 64;
  } else {
    u = local & 3; l = (local >> 2) & 31; v = (local >> 7) & 1;
    g = (local >> 8) & 3; s = local >> 10; nwb = g * 32;
  }
  int nf = 2 * v + (u >> 1);
  int jj = (l & 3) + ((u & 1) << 2);
  int n  = nwb + nf * 8 + (l >> 2);
  int k0 = s * 16 + 2 * jj;
  float v0 = (k0     < Kreal) ? src[ k0      * N + n] : 0.0f;
  float v1 = (k0 + 1 < Kreal) ? src[(k0 + 1) * N + n] : 0.0f;
  __half2 h = __floats2half2_rn(v0, v1);
  g_w[i] = *reinterpret_cast<uint32_t*>(&h);
}

// One layer: ibuf (ldmatrix) -> obuf (epilogue). Ping-pong, ONE CTA barrier per layer.
// SELF>0: rotate the k-loop to start at s0 = g*SELF — those SELF steps read only data this
// warp itself wrote last layer (needs only __syncwarp), so the CTA barrier hides behind
// ~SELF*112 cycles of MMA. Remaining steps run after __syncthreads.
template<int KH, int NCOLS, bool RELU, int SELF>
__device__ void mlp_layer(uint32_t ib_sbase, uint32_t* obuf,
                          const uint32_t* __restrict__ Wg,
                          const float* __restrict__ bias, int tid)
{
  constexpr int S  = KH / 16;
  constexpr int NT = NCOLS / 32;   // 8-neuron frags per warp (8 for 256, 4 for 128)
  constexpr int NV = NT / 2;       // LDG.128 per k-step
  constexpr int VSTEP = 32;              // uint4 stride between vector blocks
  constexpr int SSTEP = (NCOLS * 8) / 4; // uint4 stride per k16 step (all 4 groups)
  const int wid = tid >> 5, lane = tid & 31;
  const int g = wid >> 1;                       // n-group 0..3
  const int mbase = (wid & 1) * 32;             // m-block 0..1 (32 rays each)
  const int nbase = g * (NCOLS / 4);            // halves
  const int s0 = SELF ? g * SELF : 0;

  const int arow = ((lane >> 3) & 1) * 8 + (lane & 7);
  const int ksel = ((lane >> 4) & 1) * 4;       // u32
  uint32_t abase[2];
  #pragma unroll
  for (int mt = 0; mt < 2; mt++)
    abase[mt] = ib_sbase + (uint32_t)(((mbase + mt * 16 + arow) * AST + ksel) * 4);

  float acc[2][NT][4];
  #pragma unroll
  for (int mt = 0; mt < 2; mt++)
    #pragma unroll
    for (int nt = 0; nt < NT; nt++)
      #pragma unroll
      for (int j = 0; j < 4; j++) acc[mt][nt][j] = 0.0f;

  const uint4* wb4 = reinterpret_cast<const uint4*>(Wg + g * (NV * 128)) + lane;

  uint4 b[2][NV];
  uint32_t a[2][2][4];
  int s = s0;
  #pragma unroll
  for (int v = 0; v < NV; v++) b[0][v] = __ldg(wb4 + s * SSTEP + v * VSTEP);

  if (SELF > 0){
    __syncwarp();                      // own epilogue STS visible warp-wide
    ldsm4(a[0][0], abase[0] + s * 32);
    ldsm4(a[0][1], abase[1] + s * 32);
    #pragma unroll
    for (int i = 0; i < SELF; i++){
      const int cb = i & 1, nb = cb ^ 1;
      int s1 = s + 1; if (s1 == S) s1 = 0;
      #pragma unroll
      for (int v = 0; v < NV; v++) b[nb][v] = __ldg(wb4 + s1 * SSTEP + v * VSTEP);
      if (i + 1 < SELF){
        ldsm4(a[nb][0], abase[0] + s1 * 32);
        ldsm4(a[nb][1], abase[1] + s1 * 32);
      }
      #pragma unroll
      for (int nt = 0; nt < NT; nt++){
        uint32_t b0 = (nt & 1) ? b[cb][nt >> 1].z : b[cb][nt >> 1].x;
        uint32_t b1 = (nt & 1) ? b[cb][nt >> 1].w : b[cb][nt >> 1].y;
        mma_f16(acc[0][nt], a[cb][0], b0, b1);
        mma_f16(acc[1][nt], a[cb][1], b0, b1);
      }
      s = s1;
    }
  }

  __syncthreads();   // all warps' previous-layer epilogues now visible

  {  // A for the first post-barrier step (parity SELF&1 == 0 for SELF in {0,4})
    ldsm4(a[SELF & 1][0], abase[0] + s * 32);
    ldsm4(a[SELF & 1][1], abase[1] + s * 32);
  }
  #pragma unroll 2
  for (int i = SELF; i < S; i++){
    const int cb = i & 1, nb = cb ^ 1;
    if (i + 1 < S){
      int s1 = s + 1; if (s1 == S) s1 = 0;
      #pragma unroll
      for (int v = 0; v < NV; v++) b[nb][v] = __ldg(wb4 + s1 * SSTEP + v * VSTEP);
      ldsm4(a[nb][0], abase[0] + s1 * 32);
      ldsm4(a[nb][1], abase[1] + s1 * 32);
      s = s1;
    }
    #pragma unroll
    for (int nt = 0; nt < NT; nt++){
      uint32_t b0 = (nt & 1) ? b[cb][nt >> 1].z : b[cb][nt >> 1].x;
      uint32_t b1 = (nt & 1) ? b[cb][nt >> 1].w : b[cb][nt >> 1].y;
      mma_f16(acc[0][nt], a[cb][0], b0, b1);
      mma_f16(acc[1][nt], a[cb][1], b0, b1);
    }
  }

  // epilogue: bias + ReLU, pack fp16, write to the OTHER buffer (no trailing sync)
  #pragma unroll
  for (int mt = 0; mt < 2; mt++)
    #pragma unroll
    for (int nt = 0; nt < NT; nt++){
      int col  = nbase + nt * 8 + 2 * (lane & 3);          // halves (even)
      int ucol = (nbase >> 1) + nt * 4 + (lane & 3);       // u32
      float2 bb = *reinterpret_cast<const float2*>(bias + col);
      float v0 = acc[mt][nt][0] + bb.x;
      float v1 = acc[mt][nt][1] + bb.y;
      float v2 = acc[mt][nt][2] + bb.x;
      float v3 = acc[mt][nt][3] + bb.y;
      if (RELU){
        v0 = fmaxf(v0, 0.0f); v1 = fmaxf(v1, 0.0f);
        v2 = fmaxf(v2, 0.0f); v3 = fmaxf(v3, 0.0f);
      }
      __half2 h01 = __floats2half2_rn(v0, v1);
      __half2 h23 = __floats2half2_rn(v2, v3);
      int row = mbase + mt * 16 + (lane >> 2);
      obuf[row * AST + ucol]       = *reinterpret_cast<uint32_t*>(&h01);
      obuf[(row + 8) * AST + ucol] = *reinterpret_cast<uint32_t*>(&h23);
    }
}

__global__ void __launch_bounds__(256, 2)
nerf_kernel(const float* __restrict__ pos, const float* __restrict__ dir,
            const float* __restrict__ b00, const float* __restrict__ b01,
            const float* __restrict__ b02, const float* __restrict__ b03,
            const float* __restrict__ b10, const float* __restrict__ b11,
            const float* __restrict__ b12, const float* __restrict__ b13,
            const float* __restrict__ cb0, const float* __restrict__ cw1,
            const float* __restrict__ cb1,
            float* __restrict__ out, int nrays)
{
  extern __shared__ uint32_t smem_u32[];
  uint32_t* act0 = smem_u32;                  // 64 * 164  (buf0)
  uint32_t* act1 = act0 + MROWS * AST;        // 64 * 164  (buf1)
  uint32_t* deb  = act1 + MROWS * AST;        // 64 * 14 (later reused as cw1 cache)
  const uint32_t sb0 = (uint32_t)__cvta_generic_to_shared(act0);
  const uint32_t sb1 = (uint32_t)__cvta_generic_to_shared(act1);

  const int tid = threadIdx.x;

  // ---- Encodings across all 256 threads ----
  if (tid < 192){
    const int r = tid & 63, d = tid >> 6;
    const int g = blockIdx.x * MROWS + r;
    float p = pos[g * 3 + d];
    __half* rowh = reinterpret_cast<__half*>(act0 + r * AST);
    __half hp = __float2half_rn(p);
    rowh[d] = hp; rowh[256 + d] = hp;         // pe copy at halves 256.. for [z,pe] concat (buf0)
    float f = 1.0f;
    #pragma unroll
    for (int l = 0; l < 10; l++){
      float sv, cv; sincosf(p * f, &sv, &cv);
      __half hs = __float2half_rn(sv), hc = __float2half_rn(cv);
      rowh[3  + d * 10 + l] = hs; rowh[256 + 3  + d * 10 + l] = hs;
      rowh[33 + d * 10 + l] = hc; rowh[256 + 33 + d * 10 + l] = hc;
      f *= 2.0f;
    }
    if (d == 0){ rowh[63] = __half(0.0f); rowh[256 + 63] = __half(0.0f); }
  } else {
    const int r = tid - 192;
    const int g = blockIdx.x * MROWS + r;
    __half* drh = reinterpret_cast<__half*>(deb + r * 14);
    #pragma unroll
    for (int d = 0; d < 3; d++){
      float p = dir[g * 3 + d];
      drh[d] = __float2half_rn(p);
      float f = 1.0f;
      #pragma unroll
      for (int l = 0; l < 4; l++){
        float sv, cv; sincosf(p * f, &sv, &cv);
        drh[3  + d * 4 + l] = __float2half_rn(sv);
        drh[15 + d * 4 + l] = __float2half_rn(cv);
        f *= 2.0f;
      }
    }
    drh[27] = __half(0.0f);
  }
  // (no sync: L0's internal barrier covers the encode)

  // ---- MLP trunk, ping-pong; SELF=4 rotation on layers whose A was self-written ----
  mlp_layer< 64, 256, true , 0>(sb0, act1, g_w + OFF_W00, b00, tid);
  mlp_layer<256, 256, true , 4>(sb1, act0, g_w + OFF_W01, b01, tid);
  mlp_layer<256, 256, true , 4>(sb0, act1, g_w + OFF_W02, b02, tid);
  mlp_layer<256, 256, true , 4>(sb1, act0, g_w + OFF_W03, b03, tid);
  mlp_layer<320, 256, true , 4>(sb0, act1, g_w + OFF_W10, b10, tid);  // [z, pe] from buf0
  mlp_layer<256, 256, true , 4>(sb1, act0, g_w + OFF_W11, b11, tid);
  mlp_layer<256, 256, true , 4>(sb0, act1, g_w + OFF_W12, b12, tid);
  mlp_layer<256, 256, false, 4>(sb1, act0, g_w + OFF_W13, b13, tid);  // linear -> buf0

  // swap in de for [z, de] concat: buf0 u32 cols [128..144) (s=16,17: post-barrier in L8)
  if (tid < MROWS){
    uint32_t* row = act0 + tid * AST + 128;
    const uint32_t* dr = deb + tid * 14;
    #pragma unroll
    for (int j = 0; j < 14; j++) row[j] = dr[j];
    row[14] = 0u; row[15] = 0u;
  }
  // covered by L8's internal barrier

  mlp_layer<288, 128, true, 4>(sb0, act1, g_w + OFF_CW0, cb0, tid);   // [z, de] -> h in buf1

  float* csw = reinterpret_cast<float*>(deb);   // cache cw1 [128][4] in smem (deb done)
  csw[tid] = cw1[tid];
  csw[256 + tid] = cw1[256 + tid];
  __syncthreads();

  if (tid < MROWS){
    const int r = tid;
    const int g = blockIdx.x * MROWS + r;
    float o0 = cb1[0], o1 = cb1[1], o2 = cb1[2], o3 = cb1[3];
    const uint32_t* row = act1 + r * AST;
    #pragma unroll 4
    for (int j = 0; j < 64; j++){
      __half2 hu = *reinterpret_cast<const __half2*>(row + j);
      float2 hv = __half22float2(hu);
      float4 wa = reinterpret_cast<const float4*>(csw)[2*j];
      float4 wb = reinterpret_cast<const float4*>(csw)[2*j + 1];
      o0 += hv.x * wa.x + hv.y * wb.x;
      o1 += hv.x * wa.y + hv.y * wb.y;
      o2 += hv.x * wa.z + hv.y * wb.z;
      o3 += hv.x * wa.w + hv.y * wb.w;
    }
    float d  = o3;
    float sp = fmaxf(d, 0.0f) + log1pf(expf(-fabsf(d)));   // stable softplus
    out[g] = (d > 8.0f) ? d : sp;
    out[nrays + g * 3 + 0] = 1.0f / (1.0f + expf(-o0));
    out[nrays + g * 3 + 1] = 1.0f / (1.0f + expf(-o1));
    out[nrays + g * 3 + 2] = 1.0f / (1.0f + expf(-o2));
  }
}

#define SMEM_BYTES ((2 * MROWS * AST + MROWS * 14) * 4)

extern "C" void kernel_launch(void* const* d_in, const int* in_sizes, int n_in,
                              void* d_out, int out_size)
{
  const float* pos = (const float*)d_in[0];
  const float* dir = (const float*)d_in[1];
  const float* w00 = (const float*)d_in[5];  const float* b00 = (const float*)d_in[6];
  const float* w01 = (const float*)d_in[7];  const float* b01 = (const float*)d_in[8];
  const float* w02 = (const float*)d_in[9];  const float* b02 = (const float*)d_in[10];
  const float* w03 = (const float*)d_in[11]; const float* b03 = (const float*)d_in[12];
  const float* w10 = (const float*)d_in[13]; const float* b10 = (const float*)d_in[14];
  const float* w11 = (const float*)d_in[15]; const float* b11 = (const float*)d_in[16];
  const float* w12 = (const float*)d_in[17]; const float* b12 = (const float*)d_in[18];
  const float* w13 = (const float*)d_in[19]; const float* b13 = (const float*)d_in[20];
  const float* cw0 = (const float*)d_in[21]; const float* cb0 = (const float*)d_in[22];
  const float* cw1 = (const float*)d_in[23]; const float* cb1 = (const float*)d_in[24];
  float* out = (float*)d_out;

  const int nrays = in_sizes[0] / 3;

  cudaFuncSetAttribute(nerf_kernel, cudaFuncAttributeMaxDynamicSharedMemorySize, SMEM_BYTES);

  prep_all<<<(W_TOTAL + 255) / 256, 256>>>(w00, w01, w02, w03, w10, w11, w12, w13, cw0);

  nerf_kernel<<<nrays / MROWS, 256, SMEM_BYTES>>>(
      pos, dir, b00, b01, b02, b03, b10, b11, b12, b13, cb0, cw1, cb1, out, nrays);
}

// round 14
// speedup vs baseline: 1.0881x; 1.0881x over previous
#include <cuda_runtime.h>
#include <cuda_fp16.h>
#include <cstdint>
#include <math.h>

#define AST 164   // act row stride (u32); 164%32=4 -> ldmatrix 16B chunks conflict-free
#define MROWS 32  // rays per CTA (4 CTAs/SM -> 4 independent barrier domains)

// fp16 weights pre-swizzled into per-lane fragment order:
// 256-wide layers: [S16][g:4][v:4][lane:32][4 u32], cw0: [S16][g:4][v:2][lane:32][4 u32]
// vector v holds {b0(nf=2v), b1(nf=2v), b0(nf=2v+1), b1(nf=2v+1)} for mma.m16n8k16.
__device__ uint32_t g_w[264192];

#define OFF_W00 0
#define OFF_W01 8192
#define OFF_W02 40960
#define OFF_W03 73728
#define OFF_W10 106496
#define OFF_W11 147456
#define OFF_W12 180224
#define OFF_W13 212992
#define OFF_CW0 245760
#define W_TOTAL 264192

__device__ __forceinline__ void mma_f16(float* c, const uint32_t* a, uint32_t b0, uint32_t b1){
  asm volatile("mma.sync.aligned.m16n8k16.row.col.f32.f16.f16.f32 "
    "{%0,%1,%2,%3},{%4,%5,%6,%7},{%8,%9},{%0,%1,%2,%3};\n"
    : "+f"(c[0]),"+f"(c[1]),"+f"(c[2]),"+f"(c[3])
    : "r"(a[0]),"r"(a[1]),"r"(a[2]),"r"(a[3]),"r"(b0),"r"(b1));
}

__device__ __forceinline__ void ldsm4(uint32_t* r, uint32_t saddr){
  asm volatile("ldmatrix.sync.aligned.m8n8.x4.shared.b16 {%0,%1,%2,%3}, [%4];"
    : "=r"(r[0]), "=r"(r[1]), "=r"(r[2]), "=r"(r[3]) : "r"(saddr));
}

__global__ void prep_all(const float* __restrict__ w00, const float* __restrict__ w01,
                         const float* __restrict__ w02, const float* __restrict__ w03,
                         const float* __restrict__ w10, const float* __restrict__ w11,
                         const float* __restrict__ w12, const float* __restrict__ w13,
                         const float* __restrict__ cw0)
{
  int i = blockIdx.x * blockDim.x + threadIdx.x;
  if (i >= W_TOTAL) return;
  const float* src; int Kreal, N, off;
  if      (i < OFF_W01){ src=w00; Kreal= 63; N=256; off=OFF_W00; }
  else if (i < OFF_W02){ src=w01; Kreal=256; N=256; off=OFF_W01; }
  else if (i < OFF_W03){ src=w02; Kreal=256; N=256; off=OFF_W02; }
  else if (i < OFF_W10){ src=w03; Kreal=256; N=256; off=OFF_W03; }
  else if (i < OFF_W11){ src=w10; Kreal=319; N=256; off=OFF_W10; }
  else if (i < OFF_W12){ src=w11; Kreal=256; N=256; off=OFF_W11; }
  else if (i < OFF_W13){ src=w12; Kreal=256; N=256; off=OFF_W12; }
  else if (i < OFF_CW0){ src=w13; Kreal=256; N=256; off=OFF_W13; }
  else                 { src=cw0; Kreal=283; N=128; off=OFF_CW0; }
  int local = i - off;
  int u, l, v, g, s, nwb;
  if (N == 256){
    u = local & 3; l = (local >> 2) & 31; v = (local >> 7) & 3;
    g = (local >> 9) & 3; s = local >> 11; nwb = g * 64;
  } else {
    u = local & 3; l = (local >> 2) & 31; v = (local >> 7) & 1;
    g = (local >> 8) & 3; s = local >> 10; nwb = g * 32;
  }
  int nf = 2 * v + (u >> 1);
  int jj = (l & 3) + ((u & 1) << 2);
  int n  = nwb + nf * 8 + (l >> 2);
  int k0 = s * 16 + 2 * jj;
  float v0 = (k0     < Kreal) ? src[ k0      * N + n] : 0.0f;
  float v1 = (k0 + 1 < Kreal) ? src[(k0 + 1) * N + n] : 0.0f;
  __half2 h = __floats2half2_rn(v0, v1);
  g_w[i] = *reinterpret_cast<uint32_t*>(&h);
}

// One layer: ibuf (ldmatrix reads) -> obuf (epilogue writes). Ping-pong; ONE barrier per layer.
// First B chunk prefetched BEFORE the barrier so its L2 latency hides behind convergence.
// 4 warps: wid = n-group 0..3. Warp tile: 32 rays x NCOLS/4 neurons (mt=2, NT=NCOLS/32).
template<int KH, int NCOLS, bool RELU>
__device__ void mlp_layer(uint32_t ib_sbase, uint32_t* obuf,
                          const uint32_t* __restrict__ Wg,
                          const float* __restrict__ bias, int tid)
{
  constexpr int S  = KH / 16;
  constexpr int NT = NCOLS / 32;   // 8-neuron frags per warp (8 for 256, 4 for 128)
  constexpr int NV = NT / 2;       // LDG.128 per k-step
  const int wid = tid >> 5, lane = tid & 31;
  const int g = wid;                            // n-group 0..3
  const int nbase = g * (NCOLS / 4);            // halves

  const int arow = ((lane >> 3) & 1) * 8 + (lane & 7);
  const int ksel = ((lane >> 4) & 1) * 4;       // u32
  uint32_t abase[2];
  #pragma unroll
  for (int mt = 0; mt < 2; mt++)
    abase[mt] = ib_sbase + (uint32_t)(((mt * 16 + arow) * AST + ksel) * 4);

  float acc[2][NT][4];
  #pragma unroll
  for (int mt = 0; mt < 2; mt++)
    #pragma unroll
    for (int nt = 0; nt < NT; nt++)
      #pragma unroll
      for (int j = 0; j < 4; j++) acc[mt][nt][j] = 0.0f;

  const uint4* wp = reinterpret_cast<const uint4*>(Wg + g * (NV * 128)) + lane;
  constexpr int VSTEP = 32;              // uint4 stride between vector blocks
  constexpr int SSTEP = (NCOLS * 8) / 4; // uint4 stride per k16 step (all 4 groups)

  uint4 b[2][NV];
  uint32_t a[2][2][4];
  #pragma unroll
  for (int v = 0; v < NV; v++) b[0][v] = __ldg(wp + v * VSTEP);  // prefetch before barrier
  wp += SSTEP;

  __syncthreads();   // previous layer's epilogue visible; B L2 latency hidden behind convergence

  ldsm4(a[0][0], abase[0]);
  ldsm4(a[0][1], abase[1]);

  #pragma unroll 2
  for (int s = 0; s < S; s++){
    const int cb = s & 1, nb = cb ^ 1;
    if (s + 1 < S){
      #pragma unroll
      for (int v = 0; v < NV; v++) b[nb][v] = __ldg(wp + v * VSTEP);
      wp += SSTEP;
      ldsm4(a[nb][0], abase[0] + (s + 1) * 32);
      ldsm4(a[nb][1], abase[1] + (s + 1) * 32);
    }
    #pragma unroll
    for (int nt = 0; nt < NT; nt++){
      uint32_t b0 = (nt & 1) ? b[cb][nt >> 1].z : b[cb][nt >> 1].x;
      uint32_t b1 = (nt & 1) ? b[cb][nt >> 1].w : b[cb][nt >> 1].y;
      mma_f16(acc[0][nt], a[cb][0], b0, b1);
      mma_f16(acc[1][nt], a[cb][1], b0, b1);
    }
  }

  // epilogue: bias + ReLU, pack fp16, write to the OTHER buffer (no trailing sync)
  #pragma unroll
  for (int mt = 0; mt < 2; mt++)
    #pragma unroll
    for (int nt = 0; nt < NT; nt++){
      int col  = nbase + nt * 8 + 2 * (lane & 3);          // halves (even)
      int ucol = (nbase >> 1) + nt * 4 + (lane & 3);       // u32
      float2 bb = *reinterpret_cast<const float2*>(bias + col);
      float v0 = acc[mt][nt][0] + bb.x;
      float v1 = acc[mt][nt][1] + bb.y;
      float v2 = acc[mt][nt][2] + bb.x;
      float v3 = acc[mt][nt][3] + bb.y;
      if (RELU){
        v0 = fmaxf(v0, 0.0f); v1 = fmaxf(v1, 0.0f);
        v2 = fmaxf(v2, 0.0f); v3 = fmaxf(v3, 0.0f);
      }
      __half2 h01 = __floats2half2_rn(v0, v1);
      __half2 h23 = __floats2half2_rn(v2, v3);
      int row = mt * 16 + (lane >> 2);
      obuf[row * AST + ucol]       = *reinterpret_cast<uint32_t*>(&h01);
      obuf[(row + 8) * AST + ucol] = *reinterpret_cast<uint32_t*>(&h23);
    }
}

__global__ void __launch_bounds__(128, 4)
nerf_kernel(const float* __restrict__ pos, const float* __restrict__ dir,
            const float* __restrict__ b00, const float* __restrict__ b01,
            const float* __restrict__ b02, const float* __restrict__ b03,
            const float* __restrict__ b10, const float* __restrict__ b11,
            const float* __restrict__ b12, const float* __restrict__ b13,
            const float* __restrict__ cb0, const float* __restrict__ cw1,
            const float* __restrict__ cb1,
            float* __restrict__ out, int nrays)
{
  extern __shared__ uint32_t smem_u32[];
  uint32_t* act0 = smem_u32;                  // 32 * 164  (buf0)
  uint32_t* act1 = act0 + MROWS * AST;        // 32 * 164  (buf1)
  uint32_t* deb  = act1 + MROWS * AST;        // 32 * 14   (de rows)
  float*    csw  = (float*)(deb + MROWS * 14);// 512 floats (cw1 cache)
  const uint32_t sb0 = (uint32_t)__cvta_generic_to_shared(act0);
  const uint32_t sb1 = (uint32_t)__cvta_generic_to_shared(act1);

  const int tid = threadIdx.x;

  // ---- Encodings across 128 threads: [0,96) one (ray,dim) pos each; [96,128) dir per ray ----
  if (tid < 96){
    const int r = tid & 31, d = tid >> 5;
    const int g = blockIdx.x * MROWS + r;
    float p = pos[g * 3 + d];
    __half* rowh = reinterpret_cast<__half*>(act0 + r * AST);
    __half hp = __float2half_rn(p);
    rowh[d] = hp; rowh[256 + d] = hp;         // pe copy at halves 256.. for [z,pe] concat (buf0)
    float f = 1.0f;
    #pragma unroll
    for (int l = 0; l < 10; l++){
      float sv, cv; sincosf(p * f, &sv, &cv);
      __half hs = __float2half_rn(sv), hc = __float2half_rn(cv);
      rowh[3  + d * 10 + l] = hs; rowh[256 + 3  + d * 10 + l] = hs;
      rowh[33 + d * 10 + l] = hc; rowh[256 + 33 + d * 10 + l] = hc;
      f *= 2.0f;
    }
    if (d == 0){ rowh[63] = __half(0.0f); rowh[256 + 63] = __half(0.0f); }
  } else {
    const int r = tid - 96;
    const int g = blockIdx.x * MROWS + r;
    __half* drh = reinterpret_cast<__half*>(deb + r * 14);
    #pragma unroll
    for (int d = 0; d < 3; d++){
      float p = dir[g * 3 + d];
      drh[d] = __float2half_rn(p);
      float f = 1.0f;
      #pragma unroll
      for (int l = 0; l < 4; l++){
        float sv, cv; sincosf(p * f, &sv, &cv);
        drh[3  + d * 4 + l] = __float2half_rn(sv);
        drh[15 + d * 4 + l] = __float2half_rn(cv);
        f *= 2.0f;
      }
    }
    drh[27] = __half(0.0f);
  }
  // (no sync here: first mlp_layer's entry barrier covers it)

  // ---- MLP trunk, ping-pong buffers ----
  mlp_layer< 64, 256, true >(sb0, act1, g_w + OFF_W00, b00, tid);
  mlp_layer<256, 256, true >(sb1, act0, g_w + OFF_W01, b01, tid);
  mlp_layer<256, 256, true >(sb0, act1, g_w + OFF_W02, b02, tid);
  mlp_layer<256, 256, true >(sb1, act0, g_w + OFF_W03, b03, tid);
  mlp_layer<320, 256, true >(sb0, act1, g_w + OFF_W10, b10, tid);  // [z, pe] from buf0
  mlp_layer<256, 256, true >(sb1, act0, g_w + OFF_W11, b11, tid);
  mlp_layer<256, 256, true >(sb0, act1, g_w + OFF_W12, b12, tid);
  mlp_layer<256, 256, false>(sb1, act0, g_w + OFF_W13, b13, tid);  // linear -> buf0

  // swap in de for [z, de] concat: buf0 u32 cols [128..144)
  if (tid < MROWS){
    uint32_t* row = act0 + tid * AST + 128;
    const uint32_t* dr = deb + tid * 14;
    #pragma unroll
    for (int j = 0; j < 14; j++) row[j] = dr[j];
    row[14] = 0u; row[15] = 0u;
  }
  // covered by L8's entry barrier

  mlp_layer<288, 128, true>(sb0, act1, g_w + OFF_CW0, cb0, tid);   // [z, de] -> h in buf1

  // ---- head: stage cw1 to smem, then 32 threads finish their rays ----
  #pragma unroll
  for (int j = 0; j < 4; j++) csw[j * 128 + tid] = cw1[j * 128 + tid];
  __syncthreads();

  if (tid < MROWS){
    const int r = tid;
    const int g = blockIdx.x * MROWS + r;
    float o0 = cb1[0], o1 = cb1[1], o2 = cb1[2], o3 = cb1[3];
    const uint32_t* row = act1 + r * AST;
    #pragma unroll 4
    for (int j = 0; j < 64; j++){
      __half2 hu = *reinterpret_cast<const __half2*>(row + j);
      float2 hv = __half22float2(hu);
      float4 wa = reinterpret_cast<const float4*>(csw)[2*j];
      float4 wb = reinterpret_cast<const float4*>(csw)[2*j + 1];
      o0 += hv.x * wa.x + hv.y * wb.x;
      o1 += hv.x * wa.y + hv.y * wb.y;
      o2 += hv.x * wa.z + hv.y * wb.z;
      o3 += hv.x * wa.w + hv.y * wb.w;
    }
    float d  = o3;
    float sp = fmaxf(d, 0.0f) + log1pf(expf(-fabsf(d)));   // stable softplus
    out[g] = (d > 8.0f) ? d : sp;
    out[nrays + g * 3 + 0] = 1.0f / (1.0f + expf(-o0));
    out[nrays + g * 3 + 1] = 1.0f / (1.0f + expf(-o1));
    out[nrays + g * 3 + 2] = 1.0f / (1.0f + expf(-o2));
  }
}

#define SMEM_BYTES ((2 * MROWS * AST + MROWS * 14 + 512) * 4)

extern "C" void kernel_launch(void* const* d_in, const int* in_sizes, int n_in,
                              void* d_out, int out_size)
{
  const float* pos = (const float*)d_in[0];
  const float* dir = (const float*)d_in[1];
  const float* w00 = (const float*)d_in[5];  const float* b00 = (const float*)d_in[6];
  const float* w01 = (const float*)d_in[7];  const float* b01 = (const float*)d_in[8];
  const float* w02 = (const float*)d_in[9];  const float* b02 = (const float*)d_in[10];
  const float* w03 = (const float*)d_in[11]; const float* b03 = (const float*)d_in[12];
  const float* w10 = (const float*)d_in[13]; const float* b10 = (const float*)d_in[14];
  const float* w11 = (const float*)d_in[15]; const float* b11 = (const float*)d_in[16];
  const float* w12 = (const float*)d_in[17]; const float* b12 = (const float*)d_in[18];
  const float* w13 = (const float*)d_in[19]; const float* b13 = (const float*)d_in[20];
  const float* cw0 = (const float*)d_in[21]; const float* cb0 = (const float*)d_in[22];
  const float* cw1 = (const float*)d_in[23]; const float* cb1 = (const float*)d_in[24];
  float* out = (float*)d_out;

  const int nrays = in_sizes[0] / 3;

  cudaFuncSetAttribute(nerf_kernel, cudaFuncAttributeMaxDynamicSharedMemorySize, SMEM_BYTES);

  prep_all<<<(W_TOTAL + 255) / 256, 256>>>(w00, w01, w02, w03, w10, w11, w12, w13, cw0);

  nerf_kernel<<<nrays / MROWS, 128, SMEM_BYTES>>>(
      pos, dir, b00, b01, b02, b03, b10, b11, b12, b13, cb0, cw1, cb1, out, nrays);
}